// round 10
// baseline (speedup 1.0000x reference)
#include <cuda_runtime.h>
#include <cuda_bf16.h>
#include <math_constants.h>
#include <cstdint>

// Problem constants
#define NN      50000
#define NPAD    50048       // MT64 * 64
#define EE      400000
#define EP      450000      // E + N self loops
#define D_IN    6
#define HID     128
#define NH      4
#define HC      512         // NH * 128
#define LL      3
#define NHYP    4096
#define MT64    782         // ceil(NN/64)
#define SCAN_BLOCKS 49

// ---------------- device scratch (static, no allocation) ----------------
__device__ float g_h  [NN * HID];            // current node features (fp32)
__device__ __nv_bfloat16 g_a_hi[NPAD * HC];  // GEMM A operand, hi split
__device__ __nv_bfloat16 g_a_lo[NPAD * HC];
__device__ float g_as [NN * NH];
__device__ float g_ad [NN * NH];
__device__ float g_was[LL * HC];
__device__ float g_wad[LL * HC];
__device__ int   g_cnt   [NN];
__device__ int   g_rowptr[NN + 1];
__device__ int   g_cursor[NN];
__device__ int   g_srcs  [EP];
__device__ int   g_bsum  [64];
__device__ __nv_bfloat16 g_wt_hi [LL * HC * HID];  // layer Wcat^T split: [l][c*512 + k]
__device__ __nv_bfloat16 g_wt_lo [LL * HC * HID];
__device__ __nv_bfloat16 g_wte_hi[HID * HID];      // encoder W2^T split [128,128]
__device__ __nv_bfloat16 g_wte_lo[HID * HID];

// ---------------- helpers ----------------
__device__ __forceinline__ uint32_t smem_u32(const void* p) {
    uint32_t a;
    asm("{ .reg .u64 t; cvta.to.shared.u64 t, %1; cvt.u32.u64 %0, t; }" : "=r"(a) : "l"(p));
    return a;
}
__device__ __forceinline__ void ldsm_x4(uint32_t& a0, uint32_t& a1, uint32_t& a2, uint32_t& a3, uint32_t addr) {
    asm volatile("ldmatrix.sync.aligned.m8n8.x4.shared.b16 {%0,%1,%2,%3}, [%4];"
                 : "=r"(a0), "=r"(a1), "=r"(a2), "=r"(a3) : "r"(addr));
}
__device__ __forceinline__ void mma16816(float* c, const uint32_t* a, uint32_t b0, uint32_t b1) {
    asm volatile("mma.sync.aligned.m16n8k16.row.col.f32.bf16.bf16.f32 "
                 "{%0,%1,%2,%3}, {%4,%5,%6,%7}, {%8,%9}, {%0,%1,%2,%3};"
                 : "+f"(c[0]), "+f"(c[1]), "+f"(c[2]), "+f"(c[3])
                 : "r"(a[0]), "r"(a[1]), "r"(a[2]), "r"(a[3]), "r"(b0), "r"(b1));
}
#define CP_ASYNC16(dst, src) asm volatile("cp.async.cg.shared.global [%0], [%1], 16;" :: "r"(dst), "l"(src))
#define CP_COMMIT()          asm volatile("cp.async.commit_group;" ::: "memory")
#define CP_WAIT0()           asm volatile("cp.async.wait_group 0;" ::: "memory")
#define CP_WAIT1()           asm volatile("cp.async.wait_group 1;" ::: "memory")

__device__ __forceinline__ void split_bf16(float v, __nv_bfloat16& h, __nv_bfloat16& l) {
    h = __float2bfloat16(v);
    l = __float2bfloat16(v - __bfloat162float(h));
}

// smem: rows padded to 272B (136 bf16); two pipeline stages
#define ROWB  272
#define ATILE (64 * ROWB)            // 17408
#define BTILE (128 * ROWB)           // 34816
#define OFF_AHI 0
#define OFF_ALO ATILE
#define OFF_BHI (2 * ATILE)
#define OFF_BLO (2 * ATILE + BTILE)
#define STAGEB  (2 * ATILE + 2 * BTILE)    // 104448 per stage
#define SM_TOTAL (2 * STAGEB)              // 208896 -> 1 CTA/SM, double buffered
#define CS_STRIDE 133

// ================= double-buffered tensor-core GEMM + fused epilogue =================
// C[M,128] = A[M,K] @ Bt[128,K]^T, K in {128,512}, A pre-split bf16 hi/lo.
// mode 0 (encoder): y = acc + bias                         -> Cout
// mode 1 (layer):   y = relu(LN(0.25*acc + bias)) + Cout   -> Cout (residual)
// If was != null: write next-layer attn dots to g_as/g_ad.
__global__ __launch_bounds__(256) void gemm2(
        const __nv_bfloat16* __restrict__ A_hi, const __nv_bfloat16* __restrict__ A_lo,
        const __nv_bfloat16* __restrict__ Bt_hi, const __nv_bfloat16* __restrict__ Bt_lo,
        int K, int mode,
        const float* __restrict__ bias,
        const float* __restrict__ lng, const float* __restrict__ lnb,
        const float* __restrict__ was, const float* __restrict__ wad,
        float* __restrict__ Cout, int M) {
    extern __shared__ char smem[];
    __shared__ float s_was[HC], s_wad[HC];
    __shared__ float s_bias[128], s_lng[128], s_lnb[128];
    __shared__ float s_mu[64], s_rstd[64];
    const uint32_t sb = smem_u32(smem);
    const int tid = threadIdx.x, wid = tid >> 5, lane = tid & 31;
    const int rowBase = blockIdx.x * 64;
    const bool dots = (was != nullptr);

    if (tid < 128) {
        s_bias[tid] = bias[tid];
        if (mode == 1) { s_lng[tid] = lng[tid]; s_lnb[tid] = lnb[tid]; }
    }
    if (dots)
        for (int i = tid; i < HC; i += 256) { s_was[i] = was[i]; s_wad[i] = wad[i]; }

    const int wm = wid & 1, wn = wid >> 1;
    const int mW = wm * 32, nW = wn * 32;
    float acc[2][4][4];
    #pragma unroll
    for (int mi = 0; mi < 2; mi++)
        #pragma unroll
        for (int ni = 0; ni < 4; ni++)
            #pragma unroll
            for (int j = 0; j < 4; j++) acc[mi][ni][j] = 0.f;

    const int aRow  = (lane & 15);
    const int aColB = ((lane >> 4) & 1) * 16;
    const int bRow  = ((lane >> 4) & 1) * 8 + (lane & 7);
    const int bColB = ((lane >> 3) & 1) * 16;

    const int nchunks = K >> 7;

    // ---- stage loader: issue 24 cp.async for chunk ch into stage s ----
    auto load_chunk = [&](int ch, int s) {
        const int kOff = ch * 128;
        const uint32_t st = sb + (uint32_t)s * STAGEB;
        #pragma unroll
        for (int i = 0; i < 8; i++) {
            int li = tid + 256 * i;
            int row = li >> 4, c8 = (li & 15) * 8;
            size_t gidx = (size_t)row * K + kOff + c8;
            uint32_t off = (uint32_t)row * ROWB + (uint32_t)c8 * 2;
            CP_ASYNC16(st + OFF_BHI + off, &Bt_hi[gidx]);
            CP_ASYNC16(st + OFF_BLO + off, &Bt_lo[gidx]);
        }
        #pragma unroll
        for (int i = 0; i < 4; i++) {
            int li = tid + 256 * i;
            int row = li >> 4, c8 = (li & 15) * 8;
            size_t gidx = (size_t)(rowBase + row) * K + kOff + c8;
            uint32_t off = (uint32_t)row * ROWB + (uint32_t)c8 * 2;
            CP_ASYNC16(st + OFF_AHI + off, &A_hi[gidx]);
            CP_ASYNC16(st + OFF_ALO + off, &A_lo[gidx]);
        }
        CP_COMMIT();
    };

    load_chunk(0, 0);

    for (int ch = 0; ch < nchunks; ch++) {
        const int cur = ch & 1;
        if (ch + 1 < nchunks) {
            load_chunk(ch + 1, cur ^ 1);
            CP_WAIT1();
        } else {
            CP_WAIT0();
        }
        __syncthreads();

        const uint32_t st = sb + (uint32_t)cur * STAGEB;
        const uint32_t aHi = st + OFF_AHI, aLo = st + OFF_ALO;
        const uint32_t bHi = st + OFF_BHI, bLo = st + OFF_BLO;

        #pragma unroll
        for (int kb = 0; kb < 8; kb++) {
            const uint32_t kByte = kb * 32;
            uint32_t ah[2][4], al[2][4], bh[4][2], bl[4][2];
            #pragma unroll
            for (int mi = 0; mi < 2; mi++) {
                uint32_t ao = (uint32_t)(mW + mi * 16 + aRow) * ROWB + kByte + aColB;
                ldsm_x4(ah[mi][0], ah[mi][1], ah[mi][2], ah[mi][3], aHi + ao);
                ldsm_x4(al[mi][0], al[mi][1], al[mi][2], al[mi][3], aLo + ao);
            }
            #pragma unroll
            for (int nj = 0; nj < 2; nj++) {
                uint32_t bo = (uint32_t)(nW + nj * 16 + bRow) * ROWB + kByte + bColB;
                ldsm_x4(bh[nj*2][0], bh[nj*2][1], bh[nj*2+1][0], bh[nj*2+1][1], bHi + bo);
                ldsm_x4(bl[nj*2][0], bl[nj*2][1], bl[nj*2+1][0], bl[nj*2+1][1], bLo + bo);
            }
            #pragma unroll
            for (int mi = 0; mi < 2; mi++)
                #pragma unroll
                for (int ni = 0; ni < 4; ni++) {
                    mma16816(acc[mi][ni], ah[mi], bh[ni][0], bh[ni][1]);
                    mma16816(acc[mi][ni], ah[mi], bl[ni][0], bl[ni][1]);
                    mma16816(acc[mi][ni], al[mi], bh[ni][0], bh[ni][1]);
                }
        }
        __syncthreads();
    }

    // --- epilogue: acc -> smem bounce (64 x 128, stride 133, reuses stage 0) ---
    float* cs = (float*)smem;
    {
        const int r0 = (lane >> 2), c0 = (lane & 3) * 2;
        #pragma unroll
        for (int mi = 0; mi < 2; mi++)
            #pragma unroll
            for (int ni = 0; ni < 4; ni++) {
                int rr = mW + mi * 16 + r0;
                int cc = nW + ni * 8 + c0;
                cs[rr * CS_STRIDE + cc]           = acc[mi][ni][0];
                cs[rr * CS_STRIDE + cc + 1]       = acc[mi][ni][1];
                cs[(rr + 8) * CS_STRIDE + cc]     = acc[mi][ni][2];
                cs[(rr + 8) * CS_STRIDE + cc + 1] = acc[mi][ni][3];
            }
    }
    __syncthreads();

    if (mode == 0) {
        #pragma unroll
        for (int i = 0; i < 8; i++) {
            int li = tid + 256 * i;
            int row = li >> 5, c4 = (li & 31) * 4;
            int gr = rowBase + row;
            float y0 = cs[row * CS_STRIDE + c4 + 0] + s_bias[c4 + 0];
            float y1 = cs[row * CS_STRIDE + c4 + 1] + s_bias[c4 + 1];
            float y2 = cs[row * CS_STRIDE + c4 + 2] + s_bias[c4 + 2];
            float y3 = cs[row * CS_STRIDE + c4 + 3] + s_bias[c4 + 3];
            cs[row * CS_STRIDE + c4 + 0] = y0;
            cs[row * CS_STRIDE + c4 + 1] = y1;
            cs[row * CS_STRIDE + c4 + 2] = y2;
            cs[row * CS_STRIDE + c4 + 3] = y3;
            if (gr < M)
                *(float4*)&Cout[(size_t)gr * HID + c4] = make_float4(y0, y1, y2, y3);
        }
        __syncthreads();
    } else {
        #pragma unroll
        for (int i = 0; i < 8; i++) {
            int li = tid + 256 * i;
            int row = li >> 5, c4 = (li & 31) * 4;
            #pragma unroll
            for (int j = 0; j < 4; j++)
                cs[row * CS_STRIDE + c4 + j] = 0.25f * cs[row * CS_STRIDE + c4 + j] + s_bias[c4 + j];
        }
        __syncthreads();
        if (tid < 64) {
            const float* cr = cs + tid * CS_STRIDE;
            float sum = 0.f;
            #pragma unroll 8
            for (int c = 0; c < 128; c++) sum += cr[c];
            float mu = sum * (1.0f / 128.0f);
            float var = 0.f;
            #pragma unroll 8
            for (int c = 0; c < 128; c++) { float d = cr[c] - mu; var += d * d; }
            s_mu[tid] = mu;
            s_rstd[tid] = rsqrtf(var * (1.0f / 128.0f) + 1e-5f);
        }
        __syncthreads();
        #pragma unroll
        for (int i = 0; i < 8; i++) {
            int li = tid + 256 * i;
            int row = li >> 5, c4 = (li & 31) * 4;
            int gr = rowBase + row;
            float mu = s_mu[row], rs = s_rstd[row];
            float y[4];
            #pragma unroll
            for (int j = 0; j < 4; j++) {
                float v = (cs[row * CS_STRIDE + c4 + j] - mu) * rs * s_lng[c4 + j] + s_lnb[c4 + j];
                y[j] = fmaxf(v, 0.f);
            }
            if (gr < M) {
                float4 res = *(const float4*)&Cout[(size_t)gr * HID + c4];
                float4 o = make_float4(y[0] + res.x, y[1] + res.y, y[2] + res.z, y[3] + res.w);
                *(float4*)&Cout[(size_t)gr * HID + c4] = o;
                cs[row * CS_STRIDE + c4 + 0] = o.x;
                cs[row * CS_STRIDE + c4 + 1] = o.y;
                cs[row * CS_STRIDE + c4 + 2] = o.z;
                cs[row * CS_STRIDE + c4 + 3] = o.w;
            }
        }
        __syncthreads();
    }

    // --- fused attn dots for next layer ---
    if (dots && tid < 128) {
        int row = tid >> 1, cb = (tid & 1) * 64;
        int gr = rowBase + row;
        float as[4] = {0, 0, 0, 0}, ad[4] = {0, 0, 0, 0};
        const float* cr = cs + row * CS_STRIDE;
        #pragma unroll 4
        for (int c = cb; c < cb + 64; c++) {
            float y = cr[c];
            #pragma unroll
            for (int h = 0; h < 4; h++) {
                as[h] += y * s_was[h * 128 + c];
                ad[h] += y * s_wad[h * 128 + c];
            }
        }
        #pragma unroll
        for (int h = 0; h < 4; h++) {
            as[h] += __shfl_down_sync(0xFFFFFFFF, as[h], 1);
            ad[h] += __shfl_down_sync(0xFFFFFFFF, ad[h], 1);
        }
        if (((tid & 1) == 0) && gr < M) {
            #pragma unroll
            for (int h = 0; h < 4; h++) {
                g_as[gr * 4 + h] = as[h];
                g_ad[gr * 4 + h] = ad[h];
            }
        }
    }
}

// ---------------- encoder W2 transpose+split ----------------
__global__ void k_wsplit(const float* __restrict__ W, __nv_bfloat16* __restrict__ hi,
                         __nv_bfloat16* __restrict__ lo, int NC) {
    int idx = blockIdx.x * blockDim.x + threadIdx.x;
    if (idx >= NC * 128) return;
    int n = idx >> 7, k = idx & 127;
    float x = W[k * NC + n];
    split_bf16(x, hi[idx], lo[idx]);
}

// ---------------- layer Wcat^T split ----------------
__global__ void k_wsplit_cat(const float* __restrict__ gat_W) {
    int idx = blockIdx.x * blockDim.x + threadIdx.x;
    if (idx >= LL * HC * HID) return;
    int l = idx >> 16;
    int r = idx & 65535;
    int c = r >> 9;
    int k = r & 511;
    int j = k & 127, hh = k >> 7;
    float x = gat_W[(size_t)l * 65536 + j * 512 + hh * 128 + c];
    split_bf16(x, g_wt_hi[idx], g_wt_lo[idx]);
}

// ---------------- attn weight vectors ----------------
__global__ void k_wattn(const float* __restrict__ gat_W,
                        const float* __restrict__ att_src, const float* __restrict__ att_dst) {
    int idx = blockIdx.x * blockDim.x + threadIdx.x;
    if (idx >= LL * HC) return;
    int l = idx >> 9;
    int r = idx & 511;
    int hh = r >> 7, j = r & 127;
    const float* wr = gat_W + (size_t)l * 65536 + j * 512 + hh * 128;
    const float* as = att_src + l * HC + hh * 128;
    const float* ad = att_dst + l * HC + hh * 128;
    float sa = 0.f, sd = 0.f;
    #pragma unroll 8
    for (int c = 0; c < 128; c++) { sa += wr[c] * as[c]; sd += wr[c] * ad[c]; }
    g_was[idx] = sa;
    g_wad[idx] = sd;
}

// ---------------- CSR build ----------------
__global__ void k_init_counts() {
    int n = blockIdx.x * blockDim.x + threadIdx.x;
    if (n < NN) g_cnt[n] = 1;
}
__global__ void k_count(const int* __restrict__ dst) {
    int e = blockIdx.x * blockDim.x + threadIdx.x;
    if (e < EE) atomicAdd(&g_cnt[dst[e]], 1);
}
__global__ void k_scan1() {
    __shared__ int s[1024];
    int t = threadIdx.x;
    int i = blockIdx.x * 1024 + t;
    int v = (i < NN) ? g_cnt[i] : 0;
    s[t] = v;
    __syncthreads();
    #pragma unroll
    for (int off = 1; off < 1024; off <<= 1) {
        int x = (t >= off) ? s[t - off] : 0;
        __syncthreads();
        s[t] += x;
        __syncthreads();
    }
    if (i < NN) g_rowptr[i + 1] = s[t];
    if (t == 1023) g_bsum[blockIdx.x] = s[1023];
}
__global__ void k_scan2() {
    __shared__ int s[64];
    int t = threadIdx.x;
    int v = (t < SCAN_BLOCKS) ? g_bsum[t] : 0;
    s[t] = v;
    __syncthreads();
    #pragma unroll
    for (int off = 1; off < 64; off <<= 1) {
        int x = (t >= off) ? s[t - off] : 0;
        __syncthreads();
        s[t] += x;
        __syncthreads();
    }
    if (t < SCAN_BLOCKS) g_bsum[t] = s[t] - v;   // exclusive
}
__global__ void k_scan3() {
    int t = threadIdx.x;
    int i = blockIdx.x * 1024 + t;
    if (i < NN) {
        int v = g_rowptr[i + 1] + g_bsum[blockIdx.x];
        g_rowptr[i + 1] = v;
        if (i + 1 < NN) g_cursor[i + 1] = v;     // cursor fused
    }
    if (i == 0) { g_rowptr[0] = 0; g_cursor[0] = 0; }
}
__global__ void k_scatter(const int* __restrict__ ei) {
    int e = blockIdx.x * blockDim.x + threadIdx.x;
    if (e >= EP) return;
    int s, d;
    if (e < EE) { s = ei[e]; d = ei[EE + e]; }
    else        { s = e - EE; d = s; }
    int pos = atomicAdd(&g_cursor[d], 1);
    g_srcs[pos] = s;
}

// ---------------- encoder first layer (K=6), W1 in smem, writes split bf16 ----------------
__global__ __launch_bounds__(256) void k_enc1(const float* __restrict__ x,
                                              const float* __restrict__ W1,
                                              const float* __restrict__ b1) {
    __shared__ float sW[D_IN * HID], sB[HID];
    int tid = threadIdx.x;
    for (int i = tid; i < D_IN * HID; i += 256) sW[i] = W1[i];
    if (tid < HID) sB[tid] = b1[tid];
    __syncthreads();

    int gid = blockIdx.x * 256 + tid;       // node = gid>>5, 4 cols each
    if (gid >= NN * 32) return;
    int n = gid >> 5, c4 = (gid & 31) * 4;
    const float* xr = x + n * D_IN;
    float xv[D_IN];
    #pragma unroll
    for (int k = 0; k < D_IN; k++) xv[k] = xr[k];
    __nv_bfloat16 hi[4], lo[4];
    #pragma unroll
    for (int j = 0; j < 4; j++) {
        int c = c4 + j;
        float acc = sB[c];
        #pragma unroll
        for (int k = 0; k < D_IN; k++) acc += xv[k] * sW[k * HID + c];
        split_bf16(fmaxf(acc, 0.0f), hi[j], lo[j]);
    }
    *(uint2*)&g_a_hi[(size_t)n * HID + c4] = *(uint2*)hi;
    *(uint2*)&g_a_lo[(size_t)n * HID + c4] = *(uint2*)lo;
}

// ---------------- h-space aggregation -> split bf16 z (K=512 layout) ----------------
__global__ __launch_bounds__(256) void k_aggh() {
    int warp = threadIdx.x >> 5, lane = threadIdx.x & 31;
    int n = blockIdx.x * 8 + warp;
    if (n >= NN) return;
    int r0 = g_rowptr[n], r1 = g_rowptr[n + 1];

    float4 adv = *(const float4*)&g_ad[n * 4];
    float adh[4] = {adv.x, adv.y, adv.z, adv.w};

    float m[4] = {-CUDART_INF_F, -CUDART_INF_F, -CUDART_INF_F, -CUDART_INF_F};
    for (int idx = r0 + lane; idx < r1; idx += 32) {
        int s = g_srcs[idx];
        float4 asv = *(const float4*)&g_as[s * 4];
        float e0 = asv.x + adh[0]; e0 = e0 > 0 ? e0 : 0.2f * e0; m[0] = fmaxf(m[0], e0);
        float e1 = asv.y + adh[1]; e1 = e1 > 0 ? e1 : 0.2f * e1; m[1] = fmaxf(m[1], e1);
        float e2 = asv.z + adh[2]; e2 = e2 > 0 ? e2 : 0.2f * e2; m[2] = fmaxf(m[2], e2);
        float e3 = asv.w + adh[3]; e3 = e3 > 0 ? e3 : 0.2f * e3; m[3] = fmaxf(m[3], e3);
    }
    #pragma unroll
    for (int off = 16; off; off >>= 1)
        #pragma unroll
        for (int h = 0; h < 4; h++)
            m[h] = fmaxf(m[h], __shfl_xor_sync(0xFFFFFFFF, m[h], off));

    float denom[4] = {0, 0, 0, 0};
    float z[4][4];
    #pragma unroll
    for (int h = 0; h < 4; h++)
        #pragma unroll
        for (int i = 0; i < 4; i++) z[h][i] = 0.f;

    for (int idx = r0; idx < r1; idx++) {
        int s = g_srcs[idx];
        float4 asv = *(const float4*)&g_as[s * 4];
        float ex[4];
        {
            float e;
            e = asv.x + adh[0]; e = e > 0 ? e : 0.2f * e; ex[0] = __expf(e - m[0]);
            e = asv.y + adh[1]; e = e > 0 ? e : 0.2f * e; ex[1] = __expf(e - m[1]);
            e = asv.z + adh[2]; e = e > 0 ? e : 0.2f * e; ex[2] = __expf(e - m[2]);
            e = asv.w + adh[3]; e = e > 0 ? e : 0.2f * e; ex[3] = __expf(e - m[3]);
        }
        denom[0] += ex[0]; denom[1] += ex[1]; denom[2] += ex[2]; denom[3] += ex[3];
        float4 hv = *(const float4*)&g_h[(size_t)s * HID + lane * 4];
        #pragma unroll
        for (int h = 0; h < 4; h++) {
            z[h][0] += ex[h] * hv.x;
            z[h][1] += ex[h] * hv.y;
            z[h][2] += ex[h] * hv.z;
            z[h][3] += ex[h] * hv.w;
        }
    }

    #pragma unroll
    for (int h = 0; h < 4; h++) {
        float inv = 1.0f / (denom[h] + 1e-16f);
        __nv_bfloat16 hi[4], lo[4];
        #pragma unroll
        for (int i = 0; i < 4; i++) split_bf16(z[h][i] * inv, hi[i], lo[i]);
        size_t o = (size_t)n * HC + h * 128 + lane * 4;
        *(uint2*)&g_a_hi[o] = *(uint2*)hi;
        *(uint2*)&g_a_lo[o] = *(uint2*)lo;
    }
}

// ---------------- head MLP ----------------
__global__ __launch_bounds__(256) void k_head(const int* __restrict__ hyp,
                                              const float* __restrict__ W1,
                                              const float* __restrict__ b1,
                                              const float* __restrict__ W2,
                                              const float* __restrict__ b2,
                                              float* __restrict__ out) {
    int warp = threadIdx.x >> 5, lane = threadIdx.x & 31;
    int i = blockIdx.x * 8 + warp;
    if (i >= NHYP) return;
    int idx = hyp[i];
    const float* hr = g_h + (size_t)idx * HID;
    float a0 = b1[lane], a1 = b1[lane + 32];
    for (int c = 0; c < HID; c++) {
        float hv = hr[c];
        a0 += hv * W1[c * 64 + lane];
        a1 += hv * W1[c * 64 + lane + 32];
    }
    a0 = fmaxf(a0, 0.0f);
    a1 = fmaxf(a1, 0.0f);
    float p = a0 * W2[lane] + a1 * W2[lane + 32];
    #pragma unroll
    for (int off = 16; off; off >>= 1) p += __shfl_xor_sync(0xFFFFFFFF, p, off);
    if (lane == 0) out[i] = p + b2[0];
}

// ---------------- launch ----------------
extern "C" void kernel_launch(void* const* d_in, const int* in_sizes, int n_in,
                              void* d_out, int out_size) {
    const float* x        = (const float*)d_in[0];
    const int*   ei       = (const int*)  d_in[1];
    const int*   hyp      = (const int*)  d_in[2];
    const float* enc_W1   = (const float*)d_in[3];
    const float* enc_b1   = (const float*)d_in[4];
    const float* enc_W2   = (const float*)d_in[5];
    const float* enc_b2   = (const float*)d_in[6];
    const float* gat_W    = (const float*)d_in[7];
    const float* att_src  = (const float*)d_in[8];
    const float* att_dst  = (const float*)d_in[9];
    const float* gat_b    = (const float*)d_in[10];
    const float* ln_g     = (const float*)d_in[11];
    const float* ln_b     = (const float*)d_in[12];
    const float* head_W1  = (const float*)d_in[13];
    const float* head_b1  = (const float*)d_in[14];
    const float* head_W2  = (const float*)d_in[15];
    const float* head_b2  = (const float*)d_in[16];
    float* out = (float*)d_out;

    float* d_h  = nullptr; cudaGetSymbolAddress((void**)&d_h,  g_h);
    float* d_was = nullptr; cudaGetSymbolAddress((void**)&d_was, g_was);
    float* d_wad = nullptr; cudaGetSymbolAddress((void**)&d_wad, g_wad);
    __nv_bfloat16 *d_ah, *d_al, *d_wh, *d_wl, *d_weh, *d_wel;
    cudaGetSymbolAddress((void**)&d_ah,  g_a_hi);
    cudaGetSymbolAddress((void**)&d_al,  g_a_lo);
    cudaGetSymbolAddress((void**)&d_wh,  g_wt_hi);
    cudaGetSymbolAddress((void**)&d_wl,  g_wt_lo);
    cudaGetSymbolAddress((void**)&d_weh, g_wte_hi);
    cudaGetSymbolAddress((void**)&d_wel, g_wte_lo);

    static bool attr_set = false;
    if (!attr_set) {
        cudaFuncSetAttribute(gemm2, cudaFuncAttributeMaxDynamicSharedMemorySize, SM_TOTAL);
        attr_set = true;
    }

    // weight prep
    k_wsplit<<<(HID * 128 + 255) / 256, 256>>>(enc_W2, d_weh, d_wel, HID);
    k_wsplit_cat<<<(LL * HC * HID + 255) / 256, 256>>>(gat_W);
    k_wattn<<<(LL * HC + 255) / 256, 256>>>(gat_W, att_src, att_dst);
    // encoder layer 1 (writes split bf16)
    k_enc1<<<(NN * 32 + 255) / 256, 256>>>(x, enc_W1, enc_b1);
    // CSR build
    k_init_counts<<<(NN + 255) / 256, 256>>>();
    k_count<<<(EE + 255) / 256, 256>>>(ei + EE);
    k_scan1<<<SCAN_BLOCKS, 1024>>>();
    k_scan2<<<1, 64>>>();
    k_scan3<<<SCAN_BLOCKS, 1024>>>();
    k_scatter<<<(EP + 255) / 256, 256>>>(ei);

    // encoder gemm: h0 = relu1 @ W2 + b2, + attn dots for layer 0
    gemm2<<<MT64, 256, SM_TOTAL>>>(d_ah, d_al, d_weh, d_wel, HID, 0,
                                   enc_b2, nullptr, nullptr,
                                   d_was, d_wad, d_h, NN);

    // GAT layers
    for (int l = 0; l < LL; l++) {
        k_aggh<<<(NN + 7) / 8, 256>>>();
        const float* nw_s = (l + 1 < LL) ? d_was + (l + 1) * HC : nullptr;
        const float* nw_d = (l + 1 < LL) ? d_wad + (l + 1) * HC : nullptr;
        gemm2<<<MT64, 256, SM_TOTAL>>>(d_ah, d_al,
                                       d_wh + (size_t)l * HC * HID, d_wl + (size_t)l * HC * HID,
                                       HC, 1,
                                       gat_b + l * HID, ln_g + l * HID, ln_b + l * HID,
                                       nw_s, nw_d, d_h, NN);
    }

    // head MLP
    k_head<<<(NHYP + 7) / 8, 256>>>(hyp, head_W1, head_b1, head_W2, head_b2, out);
    (void)in_sizes; (void)n_in; (void)out_size;
}

// round 11
// speedup vs baseline: 1.1612x; 1.1612x over previous
#include <cuda_runtime.h>
#include <cuda_bf16.h>
#include <math_constants.h>
#include <cstdint>

// Problem constants
#define NN      50000
#define NPAD    50048       // MT64 * 64
#define EE      400000
#define EP      450000      // E + N self loops
#define D_IN    6
#define HID     128
#define NH      4
#define HC      512         // NH * 128
#define LL      3
#define NHYP    4096
#define MT64    782         // ceil(NN/64)
#define SCAN_BLOCKS 49

// ---------------- device scratch (static, no allocation) ----------------
__device__ float g_h  [NN * HID];            // current node features (fp32)
__device__ __nv_bfloat16 g_a_hi[NPAD * HC];  // GEMM A operand, hi split
__device__ __nv_bfloat16 g_a_lo[NPAD * HC];
__device__ float g_as [NN * NH];
__device__ float g_ad [NN * NH];
__device__ float g_was[LL * HC];
__device__ float g_wad[LL * HC];
__device__ int   g_cnt   [NN];
__device__ int   g_rowptr[NN + 1];
__device__ int   g_cursor[NN];
__device__ int   g_srcs  [EP];
__device__ int   g_bsum  [64];
__device__ __nv_bfloat16 g_wt_hi [LL * HC * HID];  // layer Wcat^T split: [l][c*512 + k]
__device__ __nv_bfloat16 g_wt_lo [LL * HC * HID];
__device__ __nv_bfloat16 g_wte_hi[HID * HID];      // encoder W2^T split [128,128]
__device__ __nv_bfloat16 g_wte_lo[HID * HID];

// ---------------- helpers ----------------
__device__ __forceinline__ uint32_t smem_u32(const void* p) {
    uint32_t a;
    asm("{ .reg .u64 t; cvta.to.shared.u64 t, %1; cvt.u32.u64 %0, t; }" : "=r"(a) : "l"(p));
    return a;
}
__device__ __forceinline__ void ldsm_x4(uint32_t& a0, uint32_t& a1, uint32_t& a2, uint32_t& a3, uint32_t addr) {
    asm volatile("ldmatrix.sync.aligned.m8n8.x4.shared.b16 {%0,%1,%2,%3}, [%4];"
                 : "=r"(a0), "=r"(a1), "=r"(a2), "=r"(a3) : "r"(addr));
}
__device__ __forceinline__ void mma16816(float* c, const uint32_t* a, uint32_t b0, uint32_t b1) {
    asm volatile("mma.sync.aligned.m16n8k16.row.col.f32.bf16.bf16.f32 "
                 "{%0,%1,%2,%3}, {%4,%5,%6,%7}, {%8,%9}, {%0,%1,%2,%3};"
                 : "+f"(c[0]), "+f"(c[1]), "+f"(c[2]), "+f"(c[3])
                 : "r"(a[0]), "r"(a[1]), "r"(a[2]), "r"(a[3]), "r"(b0), "r"(b1));
}
#define CP_ASYNC16(dst, src) asm volatile("cp.async.cg.shared.global [%0], [%1], 16;" :: "r"(dst), "l"(src))
#define CP_COMMIT()          asm volatile("cp.async.commit_group;" ::: "memory")
#define CP_WAIT0()           asm volatile("cp.async.wait_group 0;" ::: "memory")

__device__ __forceinline__ void split_bf16(float v, __nv_bfloat16& h, __nv_bfloat16& l) {
    h = __float2bfloat16(v);
    l = __float2bfloat16(v - __bfloat162float(h));
}

// smem: rows padded to 272B (136 bf16); single stage (2 CTAs/SM)
#define ROWB  272
#define ATILE (64 * ROWB)            // 17408
#define BTILE (128 * ROWB)           // 34816
#define OFF_AHI 0
#define OFF_ALO ATILE
#define OFF_BHI (2 * ATILE)
#define OFF_BLO (2 * ATILE + BTILE)
#define SM_TOTAL (2 * ATILE + 2 * BTILE)   // 104448 -> 2 CTAs/SM
#define CS_STRIDE 133

// ================= tensor-core GEMM + fused epilogue (R8 mainloop) =================
// C[M,128] = A[M,K] @ Bt[128,K]^T, K in {128,512}, A pre-split bf16 hi/lo.
// mode 0 (encoder): y = acc + bias                         -> Cout
// mode 1 (layer):   y = relu(LN(0.25*acc + bias)) + Cout   -> Cout (residual)
// If was != null: write next-layer attn dots to g_as/g_ad.
__global__ __launch_bounds__(256) void gemm2(
        const __nv_bfloat16* __restrict__ A_hi, const __nv_bfloat16* __restrict__ A_lo,
        const __nv_bfloat16* __restrict__ Bt_hi, const __nv_bfloat16* __restrict__ Bt_lo,
        int K, int mode,
        const float* __restrict__ bias,
        const float* __restrict__ lng, const float* __restrict__ lnb,
        const float* __restrict__ was, const float* __restrict__ wad,
        float* __restrict__ Cout, int M) {
    extern __shared__ char smem[];
    __shared__ float s_was[HC], s_wad[HC];
    __shared__ float s_bias[128], s_lng[128], s_lnb[128];
    __shared__ float s_mu[64], s_rstd[64];
    const uint32_t sb = smem_u32(smem);
    const int tid = threadIdx.x, wid = tid >> 5, lane = tid & 31;
    const int rowBase = blockIdx.x * 64;
    const bool dots = (was != nullptr);

    if (tid < 128) {
        s_bias[tid] = bias[tid];
        if (mode == 1) { s_lng[tid] = lng[tid]; s_lnb[tid] = lnb[tid]; }
    }
    if (dots)
        for (int i = tid; i < HC; i += 256) { s_was[i] = was[i]; s_wad[i] = wad[i]; }

    const int wm = wid & 1, wn = wid >> 1;
    const int mW = wm * 32, nW = wn * 32;
    float acc[2][4][4];
    #pragma unroll
    for (int mi = 0; mi < 2; mi++)
        #pragma unroll
        for (int ni = 0; ni < 4; ni++)
            #pragma unroll
            for (int j = 0; j < 4; j++) acc[mi][ni][j] = 0.f;

    const int aRow  = (lane & 15);
    const int aColB = ((lane >> 4) & 1) * 16;
    const int bRow  = ((lane >> 4) & 1) * 8 + (lane & 7);
    const int bColB = ((lane >> 3) & 1) * 16;
    const uint32_t aHi = sb + OFF_AHI, aLo = sb + OFF_ALO;
    const uint32_t bHi = sb + OFF_BHI, bLo = sb + OFF_BLO;

    const int nchunks = K >> 7;
    for (int ch = 0; ch < nchunks; ch++) {
        const int kOff = ch * 128;
        #pragma unroll
        for (int i = 0; i < 8; i++) {
            int li = tid + 256 * i;
            int row = li >> 4, c8 = (li & 15) * 8;
            size_t gidx = (size_t)row * K + kOff + c8;
            uint32_t off = (uint32_t)row * ROWB + (uint32_t)c8 * 2;
            CP_ASYNC16(sb + OFF_BHI + off, &Bt_hi[gidx]);
            CP_ASYNC16(sb + OFF_BLO + off, &Bt_lo[gidx]);
        }
        #pragma unroll
        for (int i = 0; i < 4; i++) {
            int li = tid + 256 * i;
            int row = li >> 4, c8 = (li & 15) * 8;
            size_t gidx = (size_t)(rowBase + row) * K + kOff + c8;
            uint32_t off = (uint32_t)row * ROWB + (uint32_t)c8 * 2;
            CP_ASYNC16(sb + OFF_AHI + off, &A_hi[gidx]);
            CP_ASYNC16(sb + OFF_ALO + off, &A_lo[gidx]);
        }
        CP_COMMIT();
        CP_WAIT0();
        __syncthreads();

        #pragma unroll
        for (int kb = 0; kb < 8; kb++) {
            const uint32_t kByte = kb * 32;
            uint32_t ah[2][4], al[2][4], bh[4][2], bl[4][2];
            #pragma unroll
            for (int mi = 0; mi < 2; mi++) {
                uint32_t ao = (uint32_t)(mW + mi * 16 + aRow) * ROWB + kByte + aColB;
                ldsm_x4(ah[mi][0], ah[mi][1], ah[mi][2], ah[mi][3], aHi + ao);
                ldsm_x4(al[mi][0], al[mi][1], al[mi][2], al[mi][3], aLo + ao);
            }
            #pragma unroll
            for (int nj = 0; nj < 2; nj++) {
                uint32_t bo = (uint32_t)(nW + nj * 16 + bRow) * ROWB + kByte + bColB;
                ldsm_x4(bh[nj*2][0], bh[nj*2][1], bh[nj*2+1][0], bh[nj*2+1][1], bHi + bo);
                ldsm_x4(bl[nj*2][0], bl[nj*2][1], bl[nj*2+1][0], bl[nj*2+1][1], bLo + bo);
            }
            #pragma unroll
            for (int mi = 0; mi < 2; mi++)
                #pragma unroll
                for (int ni = 0; ni < 4; ni++) {
                    mma16816(acc[mi][ni], ah[mi], bh[ni][0], bh[ni][1]);
                    mma16816(acc[mi][ni], ah[mi], bl[ni][0], bl[ni][1]);
                    mma16816(acc[mi][ni], al[mi], bh[ni][0], bh[ni][1]);
                }
        }
        __syncthreads();
    }

    // --- epilogue: acc -> smem bounce (64 x 128, stride 133) ---
    float* cs = (float*)smem;
    {
        const int r0 = (lane >> 2), c0 = (lane & 3) * 2;
        #pragma unroll
        for (int mi = 0; mi < 2; mi++)
            #pragma unroll
            for (int ni = 0; ni < 4; ni++) {
                int rr = mW + mi * 16 + r0;
                int cc = nW + ni * 8 + c0;
                cs[rr * CS_STRIDE + cc]           = acc[mi][ni][0];
                cs[rr * CS_STRIDE + cc + 1]       = acc[mi][ni][1];
                cs[(rr + 8) * CS_STRIDE + cc]     = acc[mi][ni][2];
                cs[(rr + 8) * CS_STRIDE + cc + 1] = acc[mi][ni][3];
            }
    }
    __syncthreads();

    if (mode == 0) {
        #pragma unroll
        for (int i = 0; i < 8; i++) {
            int li = tid + 256 * i;
            int row = li >> 5, c4 = (li & 31) * 4;
            int gr = rowBase + row;
            float y0 = cs[row * CS_STRIDE + c4 + 0] + s_bias[c4 + 0];
            float y1 = cs[row * CS_STRIDE + c4 + 1] + s_bias[c4 + 1];
            float y2 = cs[row * CS_STRIDE + c4 + 2] + s_bias[c4 + 2];
            float y3 = cs[row * CS_STRIDE + c4 + 3] + s_bias[c4 + 3];
            cs[row * CS_STRIDE + c4 + 0] = y0;
            cs[row * CS_STRIDE + c4 + 1] = y1;
            cs[row * CS_STRIDE + c4 + 2] = y2;
            cs[row * CS_STRIDE + c4 + 3] = y3;
            if (gr < M)
                *(float4*)&Cout[(size_t)gr * HID + c4] = make_float4(y0, y1, y2, y3);
        }
        __syncthreads();
    } else {
        #pragma unroll
        for (int i = 0; i < 8; i++) {
            int li = tid + 256 * i;
            int row = li >> 5, c4 = (li & 31) * 4;
            #pragma unroll
            for (int j = 0; j < 4; j++)
                cs[row * CS_STRIDE + c4 + j] = 0.25f * cs[row * CS_STRIDE + c4 + j] + s_bias[c4 + j];
        }
        __syncthreads();
        if (tid < 64) {
            const float* cr = cs + tid * CS_STRIDE;
            float sum = 0.f;
            #pragma unroll 8
            for (int c = 0; c < 128; c++) sum += cr[c];
            float mu = sum * (1.0f / 128.0f);
            float var = 0.f;
            #pragma unroll 8
            for (int c = 0; c < 128; c++) { float d = cr[c] - mu; var += d * d; }
            s_mu[tid] = mu;
            s_rstd[tid] = rsqrtf(var * (1.0f / 128.0f) + 1e-5f);
        }
        __syncthreads();
        #pragma unroll
        for (int i = 0; i < 8; i++) {
            int li = tid + 256 * i;
            int row = li >> 5, c4 = (li & 31) * 4;
            int gr = rowBase + row;
            float mu = s_mu[row], rs = s_rstd[row];
            float y[4];
            #pragma unroll
            for (int j = 0; j < 4; j++) {
                float v = (cs[row * CS_STRIDE + c4 + j] - mu) * rs * s_lng[c4 + j] + s_lnb[c4 + j];
                y[j] = fmaxf(v, 0.f);
            }
            if (gr < M) {
                float4 res = *(const float4*)&Cout[(size_t)gr * HID + c4];
                float4 o = make_float4(y[0] + res.x, y[1] + res.y, y[2] + res.z, y[3] + res.w);
                *(float4*)&Cout[(size_t)gr * HID + c4] = o;
                cs[row * CS_STRIDE + c4 + 0] = o.x;
                cs[row * CS_STRIDE + c4 + 1] = o.y;
                cs[row * CS_STRIDE + c4 + 2] = o.z;
                cs[row * CS_STRIDE + c4 + 3] = o.w;
            }
        }
        __syncthreads();
    }

    // --- fused attn dots for next layer ---
    if (dots && tid < 128) {
        int row = tid >> 1, cb = (tid & 1) * 64;
        int gr = rowBase + row;
        float as[4] = {0, 0, 0, 0}, ad[4] = {0, 0, 0, 0};
        const float* cr = cs + row * CS_STRIDE;
        #pragma unroll 4
        for (int c = cb; c < cb + 64; c++) {
            float y = cr[c];
            #pragma unroll
            for (int h = 0; h < 4; h++) {
                as[h] += y * s_was[h * 128 + c];
                ad[h] += y * s_wad[h * 128 + c];
            }
        }
        #pragma unroll
        for (int h = 0; h < 4; h++) {
            as[h] += __shfl_down_sync(0xFFFFFFFF, as[h], 1);
            ad[h] += __shfl_down_sync(0xFFFFFFFF, ad[h], 1);
        }
        if (((tid & 1) == 0) && gr < M) {
            #pragma unroll
            for (int h = 0; h < 4; h++) {
                g_as[gr * 4 + h] = as[h];
                g_ad[gr * 4 + h] = ad[h];
            }
        }
    }
}

// ---------------- encoder W2 transpose+split ----------------
__global__ void k_wsplit(const float* __restrict__ W, __nv_bfloat16* __restrict__ hi,
                         __nv_bfloat16* __restrict__ lo, int NC) {
    int idx = blockIdx.x * blockDim.x + threadIdx.x;
    if (idx >= NC * 128) return;
    int n = idx >> 7, k = idx & 127;
    float x = W[k * NC + n];
    split_bf16(x, hi[idx], lo[idx]);
}

// ---------------- layer Wcat^T split ----------------
__global__ void k_wsplit_cat(const float* __restrict__ gat_W) {
    int idx = blockIdx.x * blockDim.x + threadIdx.x;
    if (idx >= LL * HC * HID) return;
    int l = idx >> 16;
    int r = idx & 65535;
    int c = r >> 9;
    int k = r & 511;
    int j = k & 127, hh = k >> 7;
    float x = gat_W[(size_t)l * 65536 + j * 512 + hh * 128 + c];
    split_bf16(x, g_wt_hi[idx], g_wt_lo[idx]);
}

// ---------------- attn weight vectors ----------------
__global__ void k_wattn(const float* __restrict__ gat_W,
                        const float* __restrict__ att_src, const float* __restrict__ att_dst) {
    int idx = blockIdx.x * blockDim.x + threadIdx.x;
    if (idx >= LL * HC) return;
    int l = idx >> 9;
    int r = idx & 511;
    int hh = r >> 7, j = r & 127;
    const float* wr = gat_W + (size_t)l * 65536 + j * 512 + hh * 128;
    const float* as = att_src + l * HC + hh * 128;
    const float* ad = att_dst + l * HC + hh * 128;
    float sa = 0.f, sd = 0.f;
    #pragma unroll 8
    for (int c = 0; c < 128; c++) { sa += wr[c] * as[c]; sd += wr[c] * ad[c]; }
    g_was[idx] = sa;
    g_wad[idx] = sd;
}

// ---------------- CSR build ----------------
__global__ void k_init_counts() {
    int n = blockIdx.x * blockDim.x + threadIdx.x;
    if (n < NN) g_cnt[n] = 1;
}
__global__ void k_count(const int* __restrict__ dst) {
    int e = blockIdx.x * blockDim.x + threadIdx.x;
    if (e < EE) atomicAdd(&g_cnt[dst[e]], 1);
}
__global__ void k_scan1() {
    __shared__ int s[1024];
    int t = threadIdx.x;
    int i = blockIdx.x * 1024 + t;
    int v = (i < NN) ? g_cnt[i] : 0;
    s[t] = v;
    __syncthreads();
    #pragma unroll
    for (int off = 1; off < 1024; off <<= 1) {
        int x = (t >= off) ? s[t - off] : 0;
        __syncthreads();
        s[t] += x;
        __syncthreads();
    }
    if (i < NN) g_rowptr[i + 1] = s[t];
    if (t == 1023) g_bsum[blockIdx.x] = s[1023];
}
__global__ void k_scan2() {
    __shared__ int s[64];
    int t = threadIdx.x;
    int v = (t < SCAN_BLOCKS) ? g_bsum[t] : 0;
    s[t] = v;
    __syncthreads();
    #pragma unroll
    for (int off = 1; off < 64; off <<= 1) {
        int x = (t >= off) ? s[t - off] : 0;
        __syncthreads();
        s[t] += x;
        __syncthreads();
    }
    if (t < SCAN_BLOCKS) g_bsum[t] = s[t] - v;   // exclusive
}
__global__ void k_scan3() {
    int t = threadIdx.x;
    int i = blockIdx.x * 1024 + t;
    if (i < NN) {
        int v = g_rowptr[i + 1] + g_bsum[blockIdx.x];
        g_rowptr[i + 1] = v;
        if (i + 1 < NN) g_cursor[i + 1] = v;     // cursor fused
    }
    if (i == 0) { g_rowptr[0] = 0; g_cursor[0] = 0; }
}
__global__ void k_scatter(const int* __restrict__ ei) {
    int e = blockIdx.x * blockDim.x + threadIdx.x;
    if (e >= EP) return;
    int s, d;
    if (e < EE) { s = ei[e]; d = ei[EE + e]; }
    else        { s = e - EE; d = s; }
    int pos = atomicAdd(&g_cursor[d], 1);
    g_srcs[pos] = s;
}

// ---------------- encoder first layer (K=6), W1 in smem, writes split bf16 ----------------
__global__ __launch_bounds__(256) void k_enc1(const float* __restrict__ x,
                                              const float* __restrict__ W1,
                                              const float* __restrict__ b1) {
    __shared__ float sW[D_IN * HID], sB[HID];
    int tid = threadIdx.x;
    for (int i = tid; i < D_IN * HID; i += 256) sW[i] = W1[i];
    if (tid < HID) sB[tid] = b1[tid];
    __syncthreads();

    int gid = blockIdx.x * 256 + tid;       // node = gid>>5, 4 cols each
    if (gid >= NN * 32) return;
    int n = gid >> 5, c4 = (gid & 31) * 4;
    const float* xr = x + n * D_IN;
    float xv[D_IN];
    #pragma unroll
    for (int k = 0; k < D_IN; k++) xv[k] = xr[k];
    __nv_bfloat16 hi[4], lo[4];
    #pragma unroll
    for (int j = 0; j < 4; j++) {
        int c = c4 + j;
        float acc = sB[c];
        #pragma unroll
        for (int k = 0; k < D_IN; k++) acc += xv[k] * sW[k * HID + c];
        split_bf16(fmaxf(acc, 0.0f), hi[j], lo[j]);
    }
    *(uint2*)&g_a_hi[(size_t)n * HID + c4] = *(uint2*)hi;
    *(uint2*)&g_a_lo[(size_t)n * HID + c4] = *(uint2*)lo;
}

// ---------------- h-space aggregation -> split bf16 z (K=512 layout) ----------------
__global__ __launch_bounds__(256) void k_aggh() {
    int warp = threadIdx.x >> 5, lane = threadIdx.x & 31;
    int n = blockIdx.x * 8 + warp;
    if (n >= NN) return;
    int r0 = g_rowptr[n], r1 = g_rowptr[n + 1];

    float4 adv = *(const float4*)&g_ad[n * 4];
    float adh[4] = {adv.x, adv.y, adv.z, adv.w};

    float m[4] = {-CUDART_INF_F, -CUDART_INF_F, -CUDART_INF_F, -CUDART_INF_F};
    for (int idx = r0 + lane; idx < r1; idx += 32) {
        int s = g_srcs[idx];
        float4 asv = *(const float4*)&g_as[s * 4];
        float e0 = asv.x + adh[0]; e0 = e0 > 0 ? e0 : 0.2f * e0; m[0] = fmaxf(m[0], e0);
        float e1 = asv.y + adh[1]; e1 = e1 > 0 ? e1 : 0.2f * e1; m[1] = fmaxf(m[1], e1);
        float e2 = asv.z + adh[2]; e2 = e2 > 0 ? e2 : 0.2f * e2; m[2] = fmaxf(m[2], e2);
        float e3 = asv.w + adh[3]; e3 = e3 > 0 ? e3 : 0.2f * e3; m[3] = fmaxf(m[3], e3);
    }
    #pragma unroll
    for (int off = 16; off; off >>= 1)
        #pragma unroll
        for (int h = 0; h < 4; h++)
            m[h] = fmaxf(m[h], __shfl_xor_sync(0xFFFFFFFF, m[h], off));

    float denom[4] = {0, 0, 0, 0};
    float z[4][4];
    #pragma unroll
    for (int h = 0; h < 4; h++)
        #pragma unroll
        for (int i = 0; i < 4; i++) z[h][i] = 0.f;

    for (int idx = r0; idx < r1; idx++) {
        int s = g_srcs[idx];
        float4 asv = *(const float4*)&g_as[s * 4];
        float ex[4];
        {
            float e;
            e = asv.x + adh[0]; e = e > 0 ? e : 0.2f * e; ex[0] = __expf(e - m[0]);
            e = asv.y + adh[1]; e = e > 0 ? e : 0.2f * e; ex[1] = __expf(e - m[1]);
            e = asv.z + adh[2]; e = e > 0 ? e : 0.2f * e; ex[2] = __expf(e - m[2]);
            e = asv.w + adh[3]; e = e > 0 ? e : 0.2f * e; ex[3] = __expf(e - m[3]);
        }
        denom[0] += ex[0]; denom[1] += ex[1]; denom[2] += ex[2]; denom[3] += ex[3];
        float4 hv = *(const float4*)&g_h[(size_t)s * HID + lane * 4];
        #pragma unroll
        for (int h = 0; h < 4; h++) {
            z[h][0] += ex[h] * hv.x;
            z[h][1] += ex[h] * hv.y;
            z[h][2] += ex[h] * hv.z;
            z[h][3] += ex[h] * hv.w;
        }
    }

    #pragma unroll
    for (int h = 0; h < 4; h++) {
        float inv = 1.0f / (denom[h] + 1e-16f);
        __nv_bfloat16 hi[4], lo[4];
        #pragma unroll
        for (int i = 0; i < 4; i++) split_bf16(z[h][i] * inv, hi[i], lo[i]);
        size_t o = (size_t)n * HC + h * 128 + lane * 4;
        *(uint2*)&g_a_hi[o] = *(uint2*)hi;
        *(uint2*)&g_a_lo[o] = *(uint2*)lo;
    }
}

// ---------------- head MLP ----------------
__global__ __launch_bounds__(256) void k_head(const int* __restrict__ hyp,
                                              const float* __restrict__ W1,
                                              const float* __restrict__ b1,
                                              const float* __restrict__ W2,
                                              const float* __restrict__ b2,
                                              float* __restrict__ out) {
    int warp = threadIdx.x >> 5, lane = threadIdx.x & 31;
    int i = blockIdx.x * 8 + warp;
    if (i >= NHYP) return;
    int idx = hyp[i];
    const float* hr = g_h + (size_t)idx * HID;
    float a0 = b1[lane], a1 = b1[lane + 32];
    for (int c = 0; c < HID; c++) {
        float hv = hr[c];
        a0 += hv * W1[c * 64 + lane];
        a1 += hv * W1[c * 64 + lane + 32];
    }
    a0 = fmaxf(a0, 0.0f);
    a1 = fmaxf(a1, 0.0f);
    float p = a0 * W2[lane] + a1 * W2[lane + 32];
    #pragma unroll
    for (int off = 16; off; off >>= 1) p += __shfl_xor_sync(0xFFFFFFFF, p, off);
    if (lane == 0) out[i] = p + b2[0];
}

// ---------------- launch ----------------
extern "C" void kernel_launch(void* const* d_in, const int* in_sizes, int n_in,
                              void* d_out, int out_size) {
    const float* x        = (const float*)d_in[0];
    const int*   ei       = (const int*)  d_in[1];
    const int*   hyp      = (const int*)  d_in[2];
    const float* enc_W1   = (const float*)d_in[3];
    const float* enc_b1   = (const float*)d_in[4];
    const float* enc_W2   = (const float*)d_in[5];
    const float* enc_b2   = (const float*)d_in[6];
    const float* gat_W    = (const float*)d_in[7];
    const float* att_src  = (const float*)d_in[8];
    const float* att_dst  = (const float*)d_in[9];
    const float* gat_b    = (const float*)d_in[10];
    const float* ln_g     = (const float*)d_in[11];
    const float* ln_b     = (const float*)d_in[12];
    const float* head_W1  = (const float*)d_in[13];
    const float* head_b1  = (const float*)d_in[14];
    const float* head_W2  = (const float*)d_in[15];
    const float* head_b2  = (const float*)d_in[16];
    float* out = (float*)d_out;

    float* d_h  = nullptr; cudaGetSymbolAddress((void**)&d_h,  g_h);
    float* d_was = nullptr; cudaGetSymbolAddress((void**)&d_was, g_was);
    float* d_wad = nullptr; cudaGetSymbolAddress((void**)&d_wad, g_wad);
    __nv_bfloat16 *d_ah, *d_al, *d_wh, *d_wl, *d_weh, *d_wel;
    cudaGetSymbolAddress((void**)&d_ah,  g_a_hi);
    cudaGetSymbolAddress((void**)&d_al,  g_a_lo);
    cudaGetSymbolAddress((void**)&d_wh,  g_wt_hi);
    cudaGetSymbolAddress((void**)&d_wl,  g_wt_lo);
    cudaGetSymbolAddress((void**)&d_weh, g_wte_hi);
    cudaGetSymbolAddress((void**)&d_wel, g_wte_lo);

    static bool init_done = false;
    static cudaStream_t s2;
    static cudaEvent_t evFork, evJoin;
    if (!init_done) {
        cudaFuncSetAttribute(gemm2, cudaFuncAttributeMaxDynamicSharedMemorySize, SM_TOTAL);
        cudaStreamCreateWithFlags(&s2, cudaStreamNonBlocking);
        cudaEventCreateWithFlags(&evFork, cudaEventDisableTiming);
        cudaEventCreateWithFlags(&evJoin, cudaEventDisableTiming);
        init_done = true;
    }

    // ---- fork: CSR build + layer weight split run on s2, encoder path on stream 0 ----
    cudaEventRecord(evFork, 0);
    cudaStreamWaitEvent(s2, evFork, 0);

    // stream s2: CSR chain + layer Wcat split
    k_init_counts<<<(NN + 255) / 256, 256, 0, s2>>>();
    k_count<<<(EE + 255) / 256, 256, 0, s2>>>(ei + EE);
    k_scan1<<<SCAN_BLOCKS, 1024, 0, s2>>>();
    k_scan2<<<1, 64, 0, s2>>>();
    k_scan3<<<SCAN_BLOCKS, 1024, 0, s2>>>();
    k_scatter<<<(EP + 255) / 256, 256, 0, s2>>>(ei);
    k_wsplit_cat<<<(LL * HC * HID + 255) / 256, 256, 0, s2>>>(gat_W);

    // stream 0: encoder path
    k_wsplit<<<(HID * 128 + 255) / 256, 256>>>(enc_W2, d_weh, d_wel, HID);
    k_wattn<<<(LL * HC + 255) / 256, 256>>>(gat_W, att_src, att_dst);
    k_enc1<<<(NN * 32 + 255) / 256, 256>>>(x, enc_W1, enc_b1);
    gemm2<<<MT64, 256, SM_TOTAL>>>(d_ah, d_al, d_weh, d_wel, HID, 0,
                                   enc_b2, nullptr, nullptr,
                                   d_was, d_wad, d_h, NN);

    // ---- join: stream 0 waits for s2 before aggregation ----
    cudaEventRecord(evJoin, s2);
    cudaStreamWaitEvent(0, evJoin, 0);

    // GAT layers
    for (int l = 0; l < LL; l++) {
        k_aggh<<<(NN + 7) / 8, 256>>>();
        const float* nw_s = (l + 1 < LL) ? d_was + (l + 1) * HC : nullptr;
        const float* nw_d = (l + 1 < LL) ? d_wad + (l + 1) * HC : nullptr;
        gemm2<<<MT64, 256, SM_TOTAL>>>(d_ah, d_al,
                                       d_wh + (size_t)l * HC * HID, d_wl + (size_t)l * HC * HID,
                                       HC, 1,
                                       gat_b + l * HID, ln_g + l * HID, ln_b + l * HID,
                                       nw_s, nw_d, d_h, NN);
    }

    // head MLP
    k_head<<<(NHYP + 7) / 8, 256>>>(hyp, head_W1, head_b1, head_W2, head_b2, out);
    (void)in_sizes; (void)n_in; (void)out_size;
}